// round 6
// baseline (speedup 1.0000x reference)
#include <cuda_runtime.h>
#include <cstdint>
#include <math.h>

// Problem constants
#define B_    2
#define S_    2048
#define HID_  4096
#define H_    32
#define KVH_  8
#define D_    128
#define NREP  (H_/KVH_)                 // 4
#define QKVN  (HID_ + 2*KVH_*D_)        // 6144
#define MTOK  (B_*S_)                   // 4096

// Scratch (static device globals; no runtime allocation allowed)
__device__ float g_qkv[(size_t)MTOK * QKVN];            // [tok][6144] fp32
__device__ float g_q  [(size_t)B_*H_*S_*D_];            // tf32 bits, pre-scaled
__device__ float g_k  [(size_t)B_*KVH_*S_*D_];          // tf32 bits
__device__ float g_v  [(size_t)B_*KVH_*S_*D_];          // tf32 bits
__device__ float g_ao [(size_t)MTOK * H_*D_];           // tf32 bits
__device__ float g_ht [(size_t)MTOK * HID_];            // hidden, tf32 bits
__device__ float g_w1 [(size_t)QKVN * HID_];            // qkv_w, tf32 bits
__device__ float g_w2 [(size_t)HID_ * HID_];            // o_w, tf32 bits

__device__ __forceinline__ uint32_t f2tf32(float f) {
    uint32_t r;
    asm("cvt.rna.tf32.f32 %0, %1;" : "=r"(r) : "f"(f));
    return r;
}
__device__ __forceinline__ float ex2f(float x) {
    float y;
    asm("ex2.approx.f32 %0, %1;" : "=f"(y) : "f"(x));
    return y;
}
__device__ __forceinline__ void mma_tf32(float* c, const uint32_t* a, const uint32_t* b) {
    asm volatile(
        "mma.sync.aligned.m16n8k8.row.col.f32.tf32.tf32.f32 "
        "{%0,%1,%2,%3}, {%4,%5,%6,%7}, {%8,%9}, {%0,%1,%2,%3};"
        : "+f"(c[0]), "+f"(c[1]), "+f"(c[2]), "+f"(c[3])
        : "r"(a[0]), "r"(a[1]), "r"(a[2]), "r"(a[3]), "r"(b[0]), "r"(b[1]));
}
__device__ __forceinline__ void cp_async16(uint32_t saddr, const void* gaddr) {
    asm volatile("cp.async.cg.shared.global [%0], [%1], 16;"
                 :: "r"(saddr), "l"(gaddr) : "memory");
}

// ---------------------------------------------------------------------------
// One-time tf32 pre-convert (elementwise, vectorized)
// ---------------------------------------------------------------------------
__global__ __launch_bounds__(256) void cvt_tf32(
    const float* __restrict__ in, float* __restrict__ out, int n4)
{
    int i = blockIdx.x * 256 + threadIdx.x;
    if (i >= n4) return;
    float4 v = ((const float4*)in)[i];
    uint4 u;
    u.x = f2tf32(v.x); u.y = f2tf32(v.y); u.z = f2tf32(v.z); u.w = f2tf32(v.w);
    ((uint4*)out)[i] = u;
}

// ===========================================================================
// tf32 mma.sync GEMM (NT): C = A * B^T. A,B already tf32-bit fp32 arrays.
// 128x128 CTA tile, BK=32, 8 warps (2x4), 64x32 warp tile.
// 3-stage cp.async pipeline, ONE __syncthreads per BK=32 (64 HMMA).
// ===========================================================================
#define GBM 128
#define GBN 128
#define GBK 32
#define GSTRIDE 36                           // 32 + 4 pad (stride%32 == 4)
#define G_TILE_FLOATS (128 * GSTRIDE)        // 4608 floats = 18432 B
#define G_STAGE_FLOATS (2 * G_TILE_FLOATS)   // 36864 B
#define G_NSTAGE 3
#define G_DYN_SMEM (G_NSTAGE * G_STAGE_FLOATS * 4)   // 110592 bytes

__global__ __launch_bounds__(256, 2) void gemm_mma(
    const float* __restrict__ A, const float* __restrict__ Bm,
    float* __restrict__ C, int M, int N, int K)
{
    extern __shared__ float sdyn[];
    const uint32_t sbase = (uint32_t)__cvta_generic_to_shared(sdyn);

    const int tid  = threadIdx.x;
    const int wid  = tid >> 5;
    const int lane = tid & 31;
    const int warp_m = wid >> 2;
    const int warp_n = wid & 3;
    const int lane4 = lane >> 2;
    const int lanek = lane & 3;
    const int m0 = blockIdx.y * GBM;
    const int n0 = blockIdx.x * GBN;
    const int NK = K >> 5;                   // BK=32 tiles

    // Global->smem: row r = tid/2, 4 chunks of 16B per operand
    const int r  = tid >> 1;
    const int c0 = (tid & 1) * 4;            // chunk base 0 or 4
    const float* Ag = A  + (size_t)(m0 + r) * K;
    const float* Bg = Bm + (size_t)(n0 + r) * K;
    const uint32_t sArow = sbase + (uint32_t)r * (GSTRIDE * 4);
    const uint32_t sBrow = sArow + G_TILE_FLOATS * 4;

    // Prologue: fill stages 0,1
#pragma unroll
    for (int s = 0; s < G_NSTAGE - 1; s++) {
        uint32_t so = (uint32_t)s * (G_STAGE_FLOATS * 4);
        const float* ag = Ag + s * GBK;
        const float* bg = Bg + s * GBK;
#pragma unroll
        for (int j = 0; j < 4; j++) {
            cp_async16(sArow + so + (c0 + j) * 16, ag + (c0 + j) * 4);
            cp_async16(sBrow + so + (c0 + j) * 16, bg + (c0 + j) * 4);
        }
        asm volatile("cp.async.commit_group;" ::: "memory");
    }

    float acc[4][4][4];
#pragma unroll
    for (int i = 0; i < 4; i++)
#pragma unroll
        for (int j = 0; j < 4; j++)
#pragma unroll
            for (int t = 0; t < 4; t++) acc[i][j][t] = 0.f;

    for (int it = 0; it < NK; it++) {
        asm volatile("cp.async.wait_group %0;" :: "n"(G_NSTAGE - 2) : "memory");
        __syncthreads();   // stage it%3 ready; stage (it+2)%3 reads done last iter

        int itn = it + G_NSTAGE - 1;
        if (itn < NK) {
            uint32_t so = (uint32_t)(itn % G_NSTAGE) * (G_STAGE_FLOATS * 4);
            const float* ag = Ag + itn * GBK;
            const float* bg = Bg + itn * GBK;
#pragma unroll
            for (int j = 0; j < 4; j++) {
                cp_async16(sArow + so + (c0 + j) * 16, ag + (c0 + j) * 4);
                cp_async16(sBrow + so + (c0 + j) * 16, bg + (c0 + j) * 4);
            }
        }
        asm volatile("cp.async.commit_group;" ::: "memory");

        const uint32_t* sA = (const uint32_t*)(sdyn + (it % G_NSTAGE) * G_STAGE_FLOATS);
        const uint32_t* sB = sA + G_TILE_FLOATS;

#pragma unroll
        for (int ks = 0; ks < 4; ks++) {
            const int kb = ks * 8 + lanek;
            uint32_t af[4][4], bf[4][2];
#pragma unroll
            for (int mt = 0; mt < 4; mt++) {
                const uint32_t* ap = sA + (warp_m * 64 + mt * 16 + lane4) * GSTRIDE + kb;
                af[mt][0] = ap[0];
                af[mt][1] = ap[8 * GSTRIDE];
                af[mt][2] = ap[4];
                af[mt][3] = ap[8 * GSTRIDE + 4];
            }
#pragma unroll
            for (int nt = 0; nt < 4; nt++) {
                const uint32_t* bp = sB + (warp_n * 32 + nt * 8 + lane4) * GSTRIDE + kb;
                bf[nt][0] = bp[0];
                bf[nt][1] = bp[4];
            }
#pragma unroll
            for (int mt = 0; mt < 4; mt++)
#pragma unroll
                for (int nt = 0; nt < 4; nt++)
                    mma_tf32(acc[mt][nt], af[mt], bf[nt]);
        }
    }

#pragma unroll
    for (int mt = 0; mt < 4; mt++) {
#pragma unroll
        for (int nt = 0; nt < 4; nt++) {
            int row = m0 + warp_m * 64 + mt * 16 + lane4;
            int col = n0 + warp_n * 32 + nt * 8 + lanek * 2;
            *(float2*)&C[(size_t)row * N + col] =
                make_float2(acc[mt][nt][0], acc[mt][nt][1]);
            *(float2*)&C[(size_t)(row + 8) * N + col] =
                make_float2(acc[mt][nt][2], acc[mt][nt][3]);
        }
    }
}

// ---------------------------------------------------------------------------
// RoPE + per-head RMSNorm + scatter. Writes tf32 BIT PATTERNS into g_q/g_k/g_v
// (Q additionally pre-scaled by scale*log2e).
// ---------------------------------------------------------------------------
__global__ __launch_bounds__(128) void rope_norm(
    const float* __restrict__ cosb, const float* __restrict__ sinb,
    const float* __restrict__ qw,   const float* __restrict__ kw)
{
    int tok = blockIdx.y;
    int hh  = blockIdx.x;
    int d   = threadIdx.x;
    int b = tok / S_, s = tok % S_;
    const float* row = g_qkv + (size_t)tok * QKVN;
    const float QSC = 0.08838834764831845f * 1.4426950408889634f;

    if (hh >= H_ + KVH_) {
        int kv = hh - (H_ + KVH_);
        ((uint32_t*)g_v)[(((size_t)b * KVH_ + kv) * S_ + s) * D_ + d] =
            f2tf32(row[H_ * D_ + KVH_ * D_ + kv * D_ + d]);
        return;
    }

    float c  = cosb[((size_t)b * S_ + s) * D_ + d];
    float sn = sinb[((size_t)b * S_ + s) * D_ + d];
    int off = (hh < H_) ? hh * D_ : H_ * D_ + (hh - H_) * D_;
    float x  = row[off + d];
    float xr = (d < 64) ? -row[off + d + 64] : row[off + d - 64];
    float y  = x * c + xr * sn;

    float v2 = y * y;
#pragma unroll
    for (int o = 16; o; o >>= 1) v2 += __shfl_xor_sync(0xffffffffu, v2, o);
    __shared__ float red[4];
    if ((d & 31) == 0) red[d >> 5] = v2;
    __syncthreads();
    float tot = red[0] + red[1] + red[2] + red[3];
    float inv = rsqrtf(tot * (1.f / D_) + 1e-6f);
    float w = (hh < H_) ? qw[d] : kw[d];
    float outv = w * y * inv;

    if (hh < H_)
        ((uint32_t*)g_q)[(((size_t)b * H_ + hh) * S_ + s) * D_ + d] =
            f2tf32(outv * QSC);
    else
        ((uint32_t*)g_k)[(((size_t)b * KVH_ + (hh - H_)) * S_ + s) * D_ + d] =
            f2tf32(outv);
}

// ---------------------------------------------------------------------------
// Flash attention with tf32 mma.sync. Inputs pre-converted tf32 bits.
// BR=BC=64, D=128, 128 threads (4 warps). Output tf32 bits -> g_ao.
// ---------------------------------------------------------------------------
#define ADP 132
#define APP 68
#define ATTN_SMEM ((3 * 64 * ADP + 4 * 16 * APP) * 4)

__global__ __launch_bounds__(128) void flash_attn_mma(float* __restrict__ AO)
{
    extern __shared__ float sm[];
    float* sQ = sm;
    float* sK = sQ + 64 * ADP;
    float* sV = sK + 64 * ADP;
    float* sP = sV + 64 * ADP;

    const int b  = blockIdx.z, h = blockIdx.y;
    const int q0 = blockIdx.x * 64;
    const int kh = h / NREP;
    const float* Qg = g_q + (((size_t)b * H_ + h) * S_ + q0) * D_;
    const float* Kg = g_k + ((size_t)b * KVH_ + kh) * (size_t)S_ * D_;
    const float* Vg = g_v + ((size_t)b * KVH_ + kh) * (size_t)S_ * D_;

    const int tid  = threadIdx.x;
    const int w    = tid >> 5;
    const int lane = tid & 31;
    const int lane4 = lane >> 2;
    const int lanek = lane & 3;

    for (int e = tid; e < 64 * 32; e += 128) {
        int r = e >> 5, c = e & 31;
        *(float4*)&sQ[r * ADP + c * 4] = ((const float4*)Qg)[r * 32 + c];
    }

    float oacc[16][4];
#pragma unroll
    for (int nt = 0; nt < 16; nt++)
#pragma unroll
        for (int t = 0; t < 4; t++) oacc[nt][t] = 0.f;
    float m0 = -1e30f, m1 = -1e30f, l0 = 0.f, l1 = 0.f;

    const uint32_t* sQu = (const uint32_t*)sQ;
    const uint32_t* sKu = (const uint32_t*)sK;
    const uint32_t* sVu = (const uint32_t*)sV;
    uint32_t* sPw = (uint32_t*)sP + w * (16 * APP);

    for (int t0 = 0; t0 < S_; t0 += 64) {
        __syncthreads();
        for (int e = tid; e < 64 * 32; e += 128) {
            int r = e >> 5, c = e & 31;
            *(float4*)&sK[r * ADP + c * 4] = ((const float4*)(Kg + (size_t)t0 * D_))[r * 32 + c];
            *(float4*)&sV[r * ADP + c * 4] = ((const float4*)(Vg + (size_t)t0 * D_))[r * 32 + c];
        }
        __syncthreads();

        float sc[8][4];
#pragma unroll
        for (int nt = 0; nt < 8; nt++)
#pragma unroll
            for (int t = 0; t < 4; t++) sc[nt][t] = 0.f;

#pragma unroll
        for (int kk = 0; kk < 16; kk++) {
            uint32_t a[4];
            const uint32_t* qp = sQu + (w * 16 + lane4) * ADP + kk * 8 + lanek;
            a[0] = qp[0]; a[1] = qp[8 * ADP]; a[2] = qp[4]; a[3] = qp[8 * ADP + 4];
#pragma unroll
            for (int nt = 0; nt < 8; nt++) {
                uint32_t bb[2];
                const uint32_t* kp = sKu + (nt * 8 + lane4) * ADP + kk * 8 + lanek;
                bb[0] = kp[0]; bb[1] = kp[4];
                mma_tf32(sc[nt], a, bb);
            }
        }

        float mx0 = -1e30f, mx1 = -1e30f;
#pragma unroll
        for (int nt = 0; nt < 8; nt++) {
            mx0 = fmaxf(mx0, fmaxf(sc[nt][0], sc[nt][1]));
            mx1 = fmaxf(mx1, fmaxf(sc[nt][2], sc[nt][3]));
        }
        mx0 = fmaxf(mx0, __shfl_xor_sync(0xffffffffu, mx0, 1));
        mx0 = fmaxf(mx0, __shfl_xor_sync(0xffffffffu, mx0, 2));
        mx1 = fmaxf(mx1, __shfl_xor_sync(0xffffffffu, mx1, 1));
        mx1 = fmaxf(mx1, __shfl_xor_sync(0xffffffffu, mx1, 2));
        float mn0 = fmaxf(m0, mx0), mn1 = fmaxf(m1, mx1);
        float cr0 = ex2f(m0 - mn0), cr1 = ex2f(m1 - mn1);

        float s0 = 0.f, s1 = 0.f;
#pragma unroll
        for (int nt = 0; nt < 8; nt++) {
            float p00 = ex2f(sc[nt][0] - mn0);
            float p01 = ex2f(sc[nt][1] - mn0);
            float p10 = ex2f(sc[nt][2] - mn1);
            float p11 = ex2f(sc[nt][3] - mn1);
            s0 += p00 + p01;
            s1 += p10 + p11;
            uint2 lo = make_uint2(f2tf32(p00), f2tf32(p01));
            uint2 hi = make_uint2(f2tf32(p10), f2tf32(p11));
            *(uint2*)&sPw[lane4 * APP + nt * 8 + 2 * lanek]       = lo;
            *(uint2*)&sPw[(lane4 + 8) * APP + nt * 8 + 2 * lanek] = hi;
        }
        s0 += __shfl_xor_sync(0xffffffffu, s0, 1);
        s0 += __shfl_xor_sync(0xffffffffu, s0, 2);
        s1 += __shfl_xor_sync(0xffffffffu, s1, 1);
        s1 += __shfl_xor_sync(0xffffffffu, s1, 2);
        l0 = l0 * cr0 + s0;
        l1 = l1 * cr1 + s1;
        m0 = mn0; m1 = mn1;

#pragma unroll
        for (int nt = 0; nt < 16; nt++) {
            oacc[nt][0] *= cr0; oacc[nt][1] *= cr0;
            oacc[nt][2] *= cr1; oacc[nt][3] *= cr1;
        }
        __syncwarp();

#pragma unroll
        for (int kk = 0; kk < 8; kk++) {
            uint32_t a[4];
            const uint32_t* pp = sPw + lane4 * APP + kk * 8 + lanek;
            a[0] = pp[0]; a[1] = pp[8 * APP]; a[2] = pp[4]; a[3] = pp[8 * APP + 4];
#pragma unroll
            for (int nt = 0; nt < 16; nt++) {
                uint32_t bb[2];
                const uint32_t* vp = sVu + (kk * 8 + lanek) * ADP + nt * 8 + lane4;
                bb[0] = vp[0]; bb[1] = vp[4 * ADP];
                mma_tf32(oacc[nt], a, bb);
            }
        }
        __syncwarp();
    }

    float i0 = 1.f / l0, i1 = 1.f / l1;
    int row0 = q0 + w * 16 + lane4;
    uint32_t* O0 = (uint32_t*)AO + ((size_t)(b * S_ + row0) * H_ + h) * D_;
    uint32_t* O1 = O0 + (size_t)8 * H_ * D_;
#pragma unroll
    for (int nt = 0; nt < 16; nt++) {
        int col = nt * 8 + 2 * lanek;
        *(uint2*)&O0[col] = make_uint2(f2tf32(oacc[nt][0] * i0), f2tf32(oacc[nt][1] * i0));
        *(uint2*)&O1[col] = make_uint2(f2tf32(oacc[nt][2] * i1), f2tf32(oacc[nt][3] * i1));
    }
}

// ---------------------------------------------------------------------------
extern "C" void kernel_launch(void* const* d_in, const int* in_sizes, int n_in,
                              void* d_out, int out_size)
{
    const float* hidden = (const float*)d_in[0];
    const float* cosb   = (const float*)d_in[1];
    const float* sinb   = (const float*)d_in[2];
    const float* qkv_w  = (const float*)d_in[3];
    const float* o_w    = (const float*)d_in[4];
    const float* qnw    = (const float*)d_in[5];
    const float* knw    = (const float*)d_in[6];
    float* out = (float*)d_out;

    float *qkvp, *aop, *htp, *w1p, *w2p;
    cudaGetSymbolAddress((void**)&qkvp, g_qkv);
    cudaGetSymbolAddress((void**)&aop,  g_ao);
    cudaGetSymbolAddress((void**)&htp,  g_ht);
    cudaGetSymbolAddress((void**)&w1p,  g_w1);
    cudaGetSymbolAddress((void**)&w2p,  g_w2);

    cudaFuncSetAttribute(gemm_mma, cudaFuncAttributeMaxDynamicSharedMemorySize,
                         G_DYN_SMEM);
    cudaFuncSetAttribute(flash_attn_mma, cudaFuncAttributeMaxDynamicSharedMemorySize,
                         ATTN_SMEM);

    // 0) One-time tf32 pre-convert of GEMM inputs
    int nh = MTOK * HID_ / 4, nw1 = QKVN * HID_ / 4, nw2 = HID_ * HID_ / 4;
    cvt_tf32<<<(nh  + 255) / 256, 256>>>(hidden, htp, nh);
    cvt_tf32<<<(nw1 + 255) / 256, 256>>>(qkv_w,  w1p, nw1);
    cvt_tf32<<<(nw2 + 255) / 256, 256>>>(o_w,    w2p, nw2);

    // 1) QKV projection (tf32 mma.sync, BK=32 pipeline)
    dim3 g1(QKVN / 128, MTOK / 128);
    gemm_mma<<<g1, 256, G_DYN_SMEM>>>(htp, w1p, qkvp, MTOK, QKVN, HID_);

    // 2) RoPE + RMSNorm + scatter (emits tf32 bits)
    dim3 g2(H_ + 2 * KVH_, MTOK);
    rope_norm<<<g2, 128>>>(cosb, sinb, qnw, knw);

    // 3) Attention (tf32 mma.sync flash)
    dim3 g3(S_ / 64, H_, B_);
    flash_attn_mma<<<g3, 128, ATTN_SMEM>>>(aop);

    // 4) O projection (tf32 mma.sync)
    dim3 g4(HID_ / 128, MTOK / 128);
    gemm_mma<<<g4, 256, G_DYN_SMEM>>>(aop, w2p, out, MTOK, HID_, H_ * D_);
}

// round 7
// speedup vs baseline: 1.0001x; 1.0001x over previous
#include <cuda_runtime.h>
#include <cstdint>
#include <math.h>

// Problem constants
#define B_    2
#define S_    2048
#define HID_  4096
#define H_    32
#define KVH_  8
#define D_    128
#define NREP  (H_/KVH_)                 // 4
#define QKVN  (HID_ + 2*KVH_*D_)        // 6144
#define MTOK  (B_*S_)                   // 4096

// Scratch (static device globals; no runtime allocation allowed)
__device__ float g_qkv[(size_t)MTOK * QKVN];            // [tok][6144] fp32
__device__ float g_q  [(size_t)B_*H_*S_*D_];            // tf32 bits, pre-scaled
__device__ float g_k  [(size_t)B_*KVH_*S_*D_];          // tf32 bits
__device__ float g_v  [(size_t)B_*KVH_*S_*D_];          // tf32 bits
__device__ float g_ao [(size_t)MTOK * H_*D_];           // tf32 bits
__device__ float g_ht [(size_t)MTOK * HID_];            // hidden, tf32 bits
__device__ float g_w1 [(size_t)QKVN * HID_];            // qkv_w, tf32 bits
__device__ float g_w2 [(size_t)HID_ * HID_];            // o_w, tf32 bits

__device__ __forceinline__ uint32_t f2tf32(float f) {
    uint32_t r;
    asm("cvt.rna.tf32.f32 %0, %1;" : "=r"(r) : "f"(f));
    return r;
}
__device__ __forceinline__ float ex2f(float x) {
    float y;
    asm("ex2.approx.f32 %0, %1;" : "=f"(y) : "f"(x));
    return y;
}
__device__ __forceinline__ void mma_tf32(float* c, const uint32_t* a, const uint32_t* b) {
    asm volatile(
        "mma.sync.aligned.m16n8k8.row.col.f32.tf32.tf32.f32 "
        "{%0,%1,%2,%3}, {%4,%5,%6,%7}, {%8,%9}, {%0,%1,%2,%3};"
        : "+f"(c[0]), "+f"(c[1]), "+f"(c[2]), "+f"(c[3])
        : "r"(a[0]), "r"(a[1]), "r"(a[2]), "r"(a[3]), "r"(b[0]), "r"(b[1]));
}
__device__ __forceinline__ void cp_async16(uint32_t saddr, const void* gaddr) {
    asm volatile("cp.async.cg.shared.global [%0], [%1], 16;"
                 :: "r"(saddr), "l"(gaddr) : "memory");
}

// ---------------------------------------------------------------------------
// One-time tf32 pre-convert (elementwise, vectorized)
// ---------------------------------------------------------------------------
__global__ __launch_bounds__(256) void cvt_tf32(
    const float* __restrict__ in, float* __restrict__ out, int n4)
{
    int i = blockIdx.x * 256 + threadIdx.x;
    if (i >= n4) return;
    float4 v = ((const float4*)in)[i];
    uint4 u;
    u.x = f2tf32(v.x); u.y = f2tf32(v.y); u.z = f2tf32(v.z); u.w = f2tf32(v.w);
    ((uint4*)out)[i] = u;
}

// ===========================================================================
// tf32 mma.sync GEMM (NT): C = A * B^T. A,B already tf32-bit fp32 arrays.
// 128x128 CTA tile, BK=32, 8 warps (2x4), 64x32 warp tile, 3-stage cp.async.
// Fragment REGISTER DOUBLE BUFFERING: loads for k-substep ks+1 overlap the
// 16 MMAs of substep ks, breaking the SM-wide LDS/HMMA phase-lock.
// ===========================================================================
#define GBM 128
#define GBN 128
#define GBK 32
#define GSTRIDE 36                           // 32 + 4 pad
#define G_TILE_FLOATS (128 * GSTRIDE)        // 4608 floats
#define G_STAGE_FLOATS (2 * G_TILE_FLOATS)
#define G_NSTAGE 3
#define G_DYN_SMEM (G_NSTAGE * G_STAGE_FLOATS * 4)   // 110592 bytes

__global__ __launch_bounds__(256, 2) void gemm_mma(
    const float* __restrict__ A, const float* __restrict__ Bm,
    float* __restrict__ C, int M, int N, int K)
{
    extern __shared__ float sdyn[];
    const uint32_t sbase = (uint32_t)__cvta_generic_to_shared(sdyn);

    const int tid  = threadIdx.x;
    const int wid  = tid >> 5;
    const int lane = tid & 31;
    const int warp_m = wid >> 2;
    const int warp_n = wid & 3;
    const int lane4 = lane >> 2;
    const int lanek = lane & 3;
    const int m0 = blockIdx.y * GBM;
    const int n0 = blockIdx.x * GBN;
    const int NK = K >> 5;

    const int r  = tid >> 1;
    const int c0 = (tid & 1) * 4;
    const float* Ag = A  + (size_t)(m0 + r) * K;
    const float* Bg = Bm + (size_t)(n0 + r) * K;
    const uint32_t sArow = sbase + (uint32_t)r * (GSTRIDE * 4);
    const uint32_t sBrow = sArow + G_TILE_FLOATS * 4;

    // Prologue: fill stages 0,1
#pragma unroll
    for (int s = 0; s < G_NSTAGE - 1; s++) {
        uint32_t so = (uint32_t)s * (G_STAGE_FLOATS * 4);
        const float* ag = Ag + s * GBK;
        const float* bg = Bg + s * GBK;
#pragma unroll
        for (int j = 0; j < 4; j++) {
            cp_async16(sArow + so + (c0 + j) * 16, ag + (c0 + j) * 4);
            cp_async16(sBrow + so + (c0 + j) * 16, bg + (c0 + j) * 4);
        }
        asm volatile("cp.async.commit_group;" ::: "memory");
    }

    float acc[4][4][4];
#pragma unroll
    for (int i = 0; i < 4; i++)
#pragma unroll
        for (int j = 0; j < 4; j++)
#pragma unroll
            for (int t = 0; t < 4; t++) acc[i][j][t] = 0.f;

    // Double-buffered fragments
    uint32_t af[2][4][4], bf[2][4][2];

    const int arow_off = (warp_m * 64 + lane4) * GSTRIDE + lanek;
    const int brow_off = (warp_n * 32 + lane4) * GSTRIDE + lanek;

    for (int it = 0; it < NK; it++) {
        asm volatile("cp.async.wait_group %0;" :: "n"(G_NSTAGE - 2) : "memory");
        __syncthreads();

        int itn = it + G_NSTAGE - 1;
        if (itn < NK) {
            uint32_t so = (uint32_t)(itn % G_NSTAGE) * (G_STAGE_FLOATS * 4);
            const float* ag = Ag + itn * GBK;
            const float* bg = Bg + itn * GBK;
#pragma unroll
            for (int j = 0; j < 4; j++) {
                cp_async16(sArow + so + (c0 + j) * 16, ag + (c0 + j) * 4);
                cp_async16(sBrow + so + (c0 + j) * 16, bg + (c0 + j) * 4);
            }
        }
        asm volatile("cp.async.commit_group;" ::: "memory");

        const uint32_t* sA = (const uint32_t*)(sdyn + (it % G_NSTAGE) * G_STAGE_FLOATS);
        const uint32_t* sB = sA + G_TILE_FLOATS;

        // Load ks=0 fragments into buffer 0
#pragma unroll
        for (int mt = 0; mt < 4; mt++) {
            const uint32_t* ap = sA + arow_off + mt * (16 * GSTRIDE);
            af[0][mt][0] = ap[0];
            af[0][mt][1] = ap[8 * GSTRIDE];
            af[0][mt][2] = ap[4];
            af[0][mt][3] = ap[8 * GSTRIDE + 4];
        }
#pragma unroll
        for (int nt = 0; nt < 4; nt++) {
            const uint32_t* bp = sB + brow_off + nt * (8 * GSTRIDE);
            bf[0][nt][0] = bp[0];
            bf[0][nt][1] = bp[4];
        }

#pragma unroll
        for (int ks = 0; ks < 4; ks++) {
            const int cur = ks & 1;
            const int nxt = cur ^ 1;
            if (ks < 3) {
                const int kb = (ks + 1) * 8;
#pragma unroll
                for (int mt = 0; mt < 4; mt++) {
                    const uint32_t* ap = sA + arow_off + mt * (16 * GSTRIDE) + kb;
                    af[nxt][mt][0] = ap[0];
                    af[nxt][mt][1] = ap[8 * GSTRIDE];
                    af[nxt][mt][2] = ap[4];
                    af[nxt][mt][3] = ap[8 * GSTRIDE + 4];
                }
#pragma unroll
                for (int nt = 0; nt < 4; nt++) {
                    const uint32_t* bp = sB + brow_off + nt * (8 * GSTRIDE) + kb;
                    bf[nxt][nt][0] = bp[0];
                    bf[nxt][nt][1] = bp[4];
                }
            }
#pragma unroll
            for (int mt = 0; mt < 4; mt++)
#pragma unroll
                for (int nt = 0; nt < 4; nt++)
                    mma_tf32(acc[mt][nt], af[cur][mt], bf[cur][nt]);
        }
    }

#pragma unroll
    for (int mt = 0; mt < 4; mt++) {
#pragma unroll
        for (int nt = 0; nt < 4; nt++) {
            int row = m0 + warp_m * 64 + mt * 16 + lane4;
            int col = n0 + warp_n * 32 + nt * 8 + lanek * 2;
            *(float2*)&C[(size_t)row * N + col] =
                make_float2(acc[mt][nt][0], acc[mt][nt][1]);
            *(float2*)&C[(size_t)(row + 8) * N + col] =
                make_float2(acc[mt][nt][2], acc[mt][nt][3]);
        }
    }
}

// ---------------------------------------------------------------------------
// RoPE + per-head RMSNorm + scatter. Writes tf32 BIT PATTERNS into g_q/g_k/g_v
// (Q additionally pre-scaled by scale*log2e).
// ---------------------------------------------------------------------------
__global__ __launch_bounds__(128) void rope_norm(
    const float* __restrict__ cosb, const float* __restrict__ sinb,
    const float* __restrict__ qw,   const float* __restrict__ kw)
{
    int tok = blockIdx.y;
    int hh  = blockIdx.x;
    int d   = threadIdx.x;
    int b = tok / S_, s = tok % S_;
    const float* row = g_qkv + (size_t)tok * QKVN;
    const float QSC = 0.08838834764831845f * 1.4426950408889634f;

    if (hh >= H_ + KVH_) {
        int kv = hh - (H_ + KVH_);
        ((uint32_t*)g_v)[(((size_t)b * KVH_ + kv) * S_ + s) * D_ + d] =
            f2tf32(row[H_ * D_ + KVH_ * D_ + kv * D_ + d]);
        return;
    }

    float c  = cosb[((size_t)b * S_ + s) * D_ + d];
    float sn = sinb[((size_t)b * S_ + s) * D_ + d];
    int off = (hh < H_) ? hh * D_ : H_ * D_ + (hh - H_) * D_;
    float x  = row[off + d];
    float xr = (d < 64) ? -row[off + d + 64] : row[off + d - 64];
    float y  = x * c + xr * sn;

    float v2 = y * y;
#pragma unroll
    for (int o = 16; o; o >>= 1) v2 += __shfl_xor_sync(0xffffffffu, v2, o);
    __shared__ float red[4];
    if ((d & 31) == 0) red[d >> 5] = v2;
    __syncthreads();
    float tot = red[0] + red[1] + red[2] + red[3];
    float inv = rsqrtf(tot * (1.f / D_) + 1e-6f);
    float w = (hh < H_) ? qw[d] : kw[d];
    float outv = w * y * inv;

    if (hh < H_)
        ((uint32_t*)g_q)[(((size_t)b * H_ + hh) * S_ + s) * D_ + d] =
            f2tf32(outv * QSC);
    else
        ((uint32_t*)g_k)[(((size_t)b * KVH_ + (hh - H_)) * S_ + s) * D_ + d] =
            f2tf32(outv);
}

// ---------------------------------------------------------------------------
// Flash attention with tf32 mma.sync. Inputs pre-converted tf32 bits.
// BR=BC=64, D=128, 128 threads (4 warps). Output tf32 bits -> g_ao.
// ---------------------------------------------------------------------------
#define ADP 132
#define APP 68
#define ATTN_SMEM ((3 * 64 * ADP + 4 * 16 * APP) * 4)

__global__ __launch_bounds__(128) void flash_attn_mma(float* __restrict__ AO)
{
    extern __shared__ float sm[];
    float* sQ = sm;
    float* sK = sQ + 64 * ADP;
    float* sV = sK + 64 * ADP;
    float* sP = sV + 64 * ADP;

    const int b  = blockIdx.z, h = blockIdx.y;
    const int q0 = blockIdx.x * 64;
    const int kh = h / NREP;
    const float* Qg = g_q + (((size_t)b * H_ + h) * S_ + q0) * D_;
    const float* Kg = g_k + ((size_t)b * KVH_ + kh) * (size_t)S_ * D_;
    const float* Vg = g_v + ((size_t)b * KVH_ + kh) * (size_t)S_ * D_;

    const int tid  = threadIdx.x;
    const int w    = tid >> 5;
    const int lane = tid & 31;
    const int lane4 = lane >> 2;
    const int lanek = lane & 3;

    for (int e = tid; e < 64 * 32; e += 128) {
        int r = e >> 5, c = e & 31;
        *(float4*)&sQ[r * ADP + c * 4] = ((const float4*)Qg)[r * 32 + c];
    }

    float oacc[16][4];
#pragma unroll
    for (int nt = 0; nt < 16; nt++)
#pragma unroll
        for (int t = 0; t < 4; t++) oacc[nt][t] = 0.f;
    float m0 = -1e30f, m1 = -1e30f, l0 = 0.f, l1 = 0.f;

    const uint32_t* sQu = (const uint32_t*)sQ;
    const uint32_t* sKu = (const uint32_t*)sK;
    const uint32_t* sVu = (const uint32_t*)sV;
    uint32_t* sPw = (uint32_t*)sP + w * (16 * APP);

    for (int t0 = 0; t0 < S_; t0 += 64) {
        __syncthreads();
        for (int e = tid; e < 64 * 32; e += 128) {
            int r = e >> 5, c = e & 31;
            *(float4*)&sK[r * ADP + c * 4] = ((const float4*)(Kg + (size_t)t0 * D_))[r * 32 + c];
            *(float4*)&sV[r * ADP + c * 4] = ((const float4*)(Vg + (size_t)t0 * D_))[r * 32 + c];
        }
        __syncthreads();

        float sc[8][4];
#pragma unroll
        for (int nt = 0; nt < 8; nt++)
#pragma unroll
            for (int t = 0; t < 4; t++) sc[nt][t] = 0.f;

#pragma unroll
        for (int kk = 0; kk < 16; kk++) {
            uint32_t a[4];
            const uint32_t* qp = sQu + (w * 16 + lane4) * ADP + kk * 8 + lanek;
            a[0] = qp[0]; a[1] = qp[8 * ADP]; a[2] = qp[4]; a[3] = qp[8 * ADP + 4];
#pragma unroll
            for (int nt = 0; nt < 8; nt++) {
                uint32_t bb[2];
                const uint32_t* kp = sKu + (nt * 8 + lane4) * ADP + kk * 8 + lanek;
                bb[0] = kp[0]; bb[1] = kp[4];
                mma_tf32(sc[nt], a, bb);
            }
        }

        float mx0 = -1e30f, mx1 = -1e30f;
#pragma unroll
        for (int nt = 0; nt < 8; nt++) {
            mx0 = fmaxf(mx0, fmaxf(sc[nt][0], sc[nt][1]));
            mx1 = fmaxf(mx1, fmaxf(sc[nt][2], sc[nt][3]));
        }
        mx0 = fmaxf(mx0, __shfl_xor_sync(0xffffffffu, mx0, 1));
        mx0 = fmaxf(mx0, __shfl_xor_sync(0xffffffffu, mx0, 2));
        mx1 = fmaxf(mx1, __shfl_xor_sync(0xffffffffu, mx1, 1));
        mx1 = fmaxf(mx1, __shfl_xor_sync(0xffffffffu, mx1, 2));
        float mn0 = fmaxf(m0, mx0), mn1 = fmaxf(m1, mx1);
        float cr0 = ex2f(m0 - mn0), cr1 = ex2f(m1 - mn1);

        float s0 = 0.f, s1 = 0.f;
#pragma unroll
        for (int nt = 0; nt < 8; nt++) {
            float p00 = ex2f(sc[nt][0] - mn0);
            float p01 = ex2f(sc[nt][1] - mn0);
            float p10 = ex2f(sc[nt][2] - mn1);
            float p11 = ex2f(sc[nt][3] - mn1);
            s0 += p00 + p01;
            s1 += p10 + p11;
            uint2 lo = make_uint2(f2tf32(p00), f2tf32(p01));
            uint2 hi = make_uint2(f2tf32(p10), f2tf32(p11));
            *(uint2*)&sPw[lane4 * APP + nt * 8 + 2 * lanek]       = lo;
            *(uint2*)&sPw[(lane4 + 8) * APP + nt * 8 + 2 * lanek] = hi;
        }
        s0 += __shfl_xor_sync(0xffffffffu, s0, 1);
        s0 += __shfl_xor_sync(0xffffffffu, s0, 2);
        s1 += __shfl_xor_sync(0xffffffffu, s1, 1);
        s1 += __shfl_xor_sync(0xffffffffu, s1, 2);
        l0 = l0 * cr0 + s0;
        l1 = l1 * cr1 + s1;
        m0 = mn0; m1 = mn1;

#pragma unroll
        for (int nt = 0; nt < 16; nt++) {
            oacc[nt][0] *= cr0; oacc[nt][1] *= cr0;
            oacc[nt][2] *= cr1; oacc[nt][3] *= cr1;
        }
        __syncwarp();

#pragma unroll
        for (int kk = 0; kk < 8; kk++) {
            uint32_t a[4];
            const uint32_t* pp = sPw + lane4 * APP + kk * 8 + lanek;
            a[0] = pp[0]; a[1] = pp[8 * APP]; a[2] = pp[4]; a[3] = pp[8 * APP + 4];
#pragma unroll
            for (int nt = 0; nt < 16; nt++) {
                uint32_t bb[2];
                const uint32_t* vp = sVu + (kk * 8 + lanek) * ADP + nt * 8 + lane4;
                bb[0] = vp[0]; bb[1] = vp[4 * ADP];
                mma_tf32(oacc[nt], a, bb);
            }
        }
        __syncwarp();
    }

    float i0 = 1.f / l0, i1 = 1.f / l1;
    int row0 = q0 + w * 16 + lane4;
    uint32_t* O0 = (uint32_t*)AO + ((size_t)(b * S_ + row0) * H_ + h) * D_;
    uint32_t* O1 = O0 + (size_t)8 * H_ * D_;
#pragma unroll
    for (int nt = 0; nt < 16; nt++) {
        int col = nt * 8 + 2 * lanek;
        *(uint2*)&O0[col] = make_uint2(f2tf32(oacc[nt][0] * i0), f2tf32(oacc[nt][1] * i0));
        *(uint2*)&O1[col] = make_uint2(f2tf32(oacc[nt][2] * i1), f2tf32(oacc[nt][3] * i1));
    }
}

// ---------------------------------------------------------------------------
extern "C" void kernel_launch(void* const* d_in, const int* in_sizes, int n_in,
                              void* d_out, int out_size)
{
    const float* hidden = (const float*)d_in[0];
    const float* cosb   = (const float*)d_in[1];
    const float* sinb   = (const float*)d_in[2];
    const float* qkv_w  = (const float*)d_in[3];
    const float* o_w    = (const float*)d_in[4];
    const float* qnw    = (const float*)d_in[5];
    const float* knw    = (const float*)d_in[6];
    float* out = (float*)d_out;

    float *qkvp, *aop, *htp, *w1p, *w2p;
    cudaGetSymbolAddress((void**)&qkvp, g_qkv);
    cudaGetSymbolAddress((void**)&aop,  g_ao);
    cudaGetSymbolAddress((void**)&htp,  g_ht);
    cudaGetSymbolAddress((void**)&w1p,  g_w1);
    cudaGetSymbolAddress((void**)&w2p,  g_w2);

    cudaFuncSetAttribute(gemm_mma, cudaFuncAttributeMaxDynamicSharedMemorySize,
                         G_DYN_SMEM);
    cudaFuncSetAttribute(flash_attn_mma, cudaFuncAttributeMaxDynamicSharedMemorySize,
                         ATTN_SMEM);

    // 0) One-time tf32 pre-convert of GEMM inputs
    int nh = MTOK * HID_ / 4, nw1 = QKVN * HID_ / 4, nw2 = HID_ * HID_ / 4;
    cvt_tf32<<<(nh  + 255) / 256, 256>>>(hidden, htp, nh);
    cvt_tf32<<<(nw1 + 255) / 256, 256>>>(qkv_w,  w1p, nw1);
    cvt_tf32<<<(nw2 + 255) / 256, 256>>>(o_w,    w2p, nw2);

    // 1) QKV projection (tf32 mma.sync, dbl-buffered fragments)
    dim3 g1(QKVN / 128, MTOK / 128);
    gemm_mma<<<g1, 256, G_DYN_SMEM>>>(htp, w1p, qkvp, MTOK, QKVN, HID_);

    // 2) RoPE + RMSNorm + scatter (emits tf32 bits)
    dim3 g2(H_ + 2 * KVH_, MTOK);
    rope_norm<<<g2, 128>>>(cosb, sinb, qnw, knw);

    // 3) Attention (tf32 mma.sync flash)
    dim3 g3(S_ / 64, H_, B_);
    flash_attn_mma<<<g3, 128, ATTN_SMEM>>>(aop);

    // 4) O projection (tf32 mma.sync)
    dim3 g4(HID_ / 128, MTOK / 128);
    gemm_mma<<<g4, 256, G_DYN_SMEM>>>(aop, w2p, out, MTOK, HID_, H_ * D_);
}

// round 8
// speedup vs baseline: 1.2692x; 1.2690x over previous
#include <cuda_runtime.h>
#include <cstdint>
#include <math.h>

// Problem constants
#define B_    2
#define S_    2048
#define HID_  4096
#define H_    32
#define KVH_  8
#define D_    128
#define NREP  (H_/KVH_)                 // 4
#define QKVN  (HID_ + 2*KVH_*D_)        // 6144
#define MTOK  (B_*S_)                   // 4096

// Scratch (static device globals; no runtime allocation allowed)
__device__ float g_qkv[(size_t)MTOK * QKVN];            // [tok][6144] fp32
__device__ float g_q  [(size_t)B_*H_*S_*D_];            // tf32 bits, pre-scaled
__device__ float g_k  [(size_t)B_*KVH_*S_*D_];          // tf32 bits
__device__ float g_v  [(size_t)B_*KVH_*S_*D_];          // tf32 bits
__device__ float g_ao [(size_t)MTOK * H_*D_];           // tf32 bits
__device__ float g_ht [(size_t)MTOK * HID_];            // hidden, tf32 bits
__device__ float g_w1 [(size_t)QKVN * HID_];            // qkv_w, tf32 bits
__device__ float g_w2 [(size_t)HID_ * HID_];            // o_w, tf32 bits

__device__ __forceinline__ uint32_t f2tf32(float f) {
    uint32_t r;
    asm("cvt.rna.tf32.f32 %0, %1;" : "=r"(r) : "f"(f));
    return r;
}
__device__ __forceinline__ float ex2f(float x) {
    float y;
    asm("ex2.approx.f32 %0, %1;" : "=f"(y) : "f"(x));
    return y;
}
__device__ __forceinline__ void mma_tf32(float* c, const uint32_t* a, const uint32_t* b) {
    asm volatile(
        "mma.sync.aligned.m16n8k8.row.col.f32.tf32.tf32.f32 "
        "{%0,%1,%2,%3}, {%4,%5,%6,%7}, {%8,%9}, {%0,%1,%2,%3};"
        : "+f"(c[0]), "+f"(c[1]), "+f"(c[2]), "+f"(c[3])
        : "r"(a[0]), "r"(a[1]), "r"(a[2]), "r"(a[3]), "r"(b[0]), "r"(b[1]));
}
__device__ __forceinline__ void cp_async16(uint32_t saddr, const void* gaddr) {
    asm volatile("cp.async.cg.shared.global [%0], [%1], 16;"
                 :: "r"(saddr), "l"(gaddr) : "memory");
}

// ---------------------------------------------------------------------------
// One-time tf32 pre-convert (elementwise, vectorized)
// ---------------------------------------------------------------------------
__global__ __launch_bounds__(256) void cvt_tf32(
    const float* __restrict__ in, float* __restrict__ out, int n4)
{
    int i = blockIdx.x * 256 + threadIdx.x;
    if (i >= n4) return;
    float4 v = ((const float4*)in)[i];
    uint4 u;
    u.x = f2tf32(v.x); u.y = f2tf32(v.y); u.z = f2tf32(v.z); u.w = f2tf32(v.w);
    ((uint4*)out)[i] = u;
}

// ===========================================================================
// tf32 mma.sync GEMM (NT): C = A * B^T, inputs pre-rounded tf32 bits.
// CTA tile 128x64, 8 warps in 4x2 grid, warp tile 32x32 (32 acc regs ->
// 3 CTAs/SM = 24 warps for latency hiding). BK=16, 4-stage cp.async,
// single __syncthreads per K-iter.
// ===========================================================================
#define GBM 128
#define GBN 64
#define GBK 16
#define GSTRIDE 20
#define GA_FLOATS (GBM * GSTRIDE)               // 2560
#define GB_FLOATS (GBN * GSTRIDE)               // 1280
#define G_STAGE_FLOATS (GA_FLOATS + GB_FLOATS)  // 3840 floats = 15360 B
#define G_NSTAGE 4
#define G_DYN_SMEM (G_NSTAGE * G_STAGE_FLOATS * 4)   // 61440 bytes

__global__ __launch_bounds__(256, 3) void gemm_mma(
    const float* __restrict__ A, const float* __restrict__ Bm,
    float* __restrict__ C, int M, int N, int K)
{
    extern __shared__ float sdyn[];
    const uint32_t sbase = (uint32_t)__cvta_generic_to_shared(sdyn);

    const int tid  = threadIdx.x;
    const int wid  = tid >> 5;
    const int lane = tid & 31;
    const int warp_m = wid >> 1;          // 0..3
    const int warp_n = wid & 1;           // 0..1
    const int lane4 = lane >> 2;          // 0..7
    const int lanek = lane & 3;           // 0..3
    const int m0 = blockIdx.y * GBM;
    const int n0 = blockIdx.x * GBN;
    const int NK = K >> 4;

    // Global->smem: A rows via tid/2 (2 chunks each), B rows via tid/4 (1 chunk)
    const int ra  = tid >> 1;
    const int ca  = (tid & 1) * 2;
    const int rb  = tid >> 2;
    const int cb  = tid & 3;
    const float* Ag = A  + (size_t)(m0 + ra) * K;
    const float* Bg = Bm + (size_t)(n0 + rb) * K;
    const uint32_t sArow = sbase + (uint32_t)ra * (GSTRIDE * 4);
    const uint32_t sBrow = sbase + GA_FLOATS * 4 + (uint32_t)rb * (GSTRIDE * 4);

    // Prologue: fill stages 0..2
#pragma unroll
    for (int s = 0; s < G_NSTAGE - 1; s++) {
        uint32_t so = (uint32_t)s * (G_STAGE_FLOATS * 4);
        cp_async16(sArow + so + (ca    ) * 16, Ag + s * GBK + (ca    ) * 4);
        cp_async16(sArow + so + (ca + 1) * 16, Ag + s * GBK + (ca + 1) * 4);
        cp_async16(sBrow + so + cb * 16,       Bg + s * GBK + cb * 4);
        asm volatile("cp.async.commit_group;" ::: "memory");
    }

    float acc[2][4][4];
#pragma unroll
    for (int i = 0; i < 2; i++)
#pragma unroll
        for (int j = 0; j < 4; j++)
#pragma unroll
            for (int t = 0; t < 4; t++) acc[i][j][t] = 0.f;

    const int arow_off = (warp_m * 32 + lane4) * GSTRIDE + lanek;
    const int brow_off = (warp_n * 32 + lane4) * GSTRIDE + lanek;

    for (int it = 0; it < NK; it++) {
        asm volatile("cp.async.wait_group %0;" :: "n"(G_NSTAGE - 2) : "memory");
        __syncthreads();

        int itn = it + G_NSTAGE - 1;
        if (itn < NK) {
            uint32_t so = (uint32_t)(itn % G_NSTAGE) * (G_STAGE_FLOATS * 4);
            cp_async16(sArow + so + (ca    ) * 16, Ag + itn * GBK + (ca    ) * 4);
            cp_async16(sArow + so + (ca + 1) * 16, Ag + itn * GBK + (ca + 1) * 4);
            cp_async16(sBrow + so + cb * 16,       Bg + itn * GBK + cb * 4);
        }
        asm volatile("cp.async.commit_group;" ::: "memory");

        const uint32_t* sA = (const uint32_t*)(sdyn + (it % G_NSTAGE) * G_STAGE_FLOATS);
        const uint32_t* sB = sA + GA_FLOATS;

#pragma unroll
        for (int ks = 0; ks < 2; ks++) {
            const int kb = ks * 8;
            uint32_t af[2][4], bf[4][2];
#pragma unroll
            for (int mt = 0; mt < 2; mt++) {
                const uint32_t* ap = sA + arow_off + mt * (16 * GSTRIDE) + kb;
                af[mt][0] = ap[0];
                af[mt][1] = ap[8 * GSTRIDE];
                af[mt][2] = ap[4];
                af[mt][3] = ap[8 * GSTRIDE + 4];
            }
#pragma unroll
            for (int nt = 0; nt < 4; nt++) {
                const uint32_t* bp = sB + brow_off + nt * (8 * GSTRIDE) + kb;
                bf[nt][0] = bp[0];
                bf[nt][1] = bp[4];
            }
#pragma unroll
            for (int mt = 0; mt < 2; mt++)
#pragma unroll
                for (int nt = 0; nt < 4; nt++)
                    mma_tf32(acc[mt][nt], af[mt], bf[nt]);
        }
    }

#pragma unroll
    for (int mt = 0; mt < 2; mt++) {
#pragma unroll
        for (int nt = 0; nt < 4; nt++) {
            int row = m0 + warp_m * 32 + mt * 16 + lane4;
            int col = n0 + warp_n * 32 + nt * 8 + lanek * 2;
            *(float2*)&C[(size_t)row * N + col] =
                make_float2(acc[mt][nt][0], acc[mt][nt][1]);
            *(float2*)&C[(size_t)(row + 8) * N + col] =
                make_float2(acc[mt][nt][2], acc[mt][nt][3]);
        }
    }
}

// ---------------------------------------------------------------------------
// RoPE + per-head RMSNorm + scatter. Writes tf32 BIT PATTERNS into g_q/g_k/g_v
// (Q additionally pre-scaled by scale*log2e).
// ---------------------------------------------------------------------------
__global__ __launch_bounds__(128) void rope_norm(
    const float* __restrict__ cosb, const float* __restrict__ sinb,
    const float* __restrict__ qw,   const float* __restrict__ kw)
{
    int tok = blockIdx.y;
    int hh  = blockIdx.x;
    int d   = threadIdx.x;
    int b = tok / S_, s = tok % S_;
    const float* row = g_qkv + (size_t)tok * QKVN;
    const float QSC = 0.08838834764831845f * 1.4426950408889634f;

    if (hh >= H_ + KVH_) {
        int kv = hh - (H_ + KVH_);
        ((uint32_t*)g_v)[(((size_t)b * KVH_ + kv) * S_ + s) * D_ + d] =
            f2tf32(row[H_ * D_ + KVH_ * D_ + kv * D_ + d]);
        return;
    }

    float c  = cosb[((size_t)b * S_ + s) * D_ + d];
    float sn = sinb[((size_t)b * S_ + s) * D_ + d];
    int off = (hh < H_) ? hh * D_ : H_ * D_ + (hh - H_) * D_;
    float x  = row[off + d];
    float xr = (d < 64) ? -row[off + d + 64] : row[off + d - 64];
    float y  = x * c + xr * sn;

    float v2 = y * y;
#pragma unroll
    for (int o = 16; o; o >>= 1) v2 += __shfl_xor_sync(0xffffffffu, v2, o);
    __shared__ float red[4];
    if ((d & 31) == 0) red[d >> 5] = v2;
    __syncthreads();
    float tot = red[0] + red[1] + red[2] + red[3];
    float inv = rsqrtf(tot * (1.f / D_) + 1e-6f);
    float w = (hh < H_) ? qw[d] : kw[d];
    float outv = w * y * inv;

    if (hh < H_)
        ((uint32_t*)g_q)[(((size_t)b * H_ + hh) * S_ + s) * D_ + d] =
            f2tf32(outv * QSC);
    else
        ((uint32_t*)g_k)[(((size_t)b * KVH_ + (hh - H_)) * S_ + s) * D_ + d] =
            f2tf32(outv);
}

// ---------------------------------------------------------------------------
// Flash attention with tf32 mma.sync. BR=128 (8 warps, 256 threads), BC=64,
// D=128. Inputs pre-converted tf32 bits. Output tf32 bits -> g_ao.
// Each warp owns 16 query rows; per-warp P tile in smem; halved K/V traffic
// vs BR=64 and doubled warps/SM.
// ---------------------------------------------------------------------------
#define FBR 128
#define ADP 132
#define APP 68
#define ATTN_SMEM ((FBR * ADP + 2 * 64 * ADP + 8 * 16 * APP) * 4)  // 169984 B

__global__ __launch_bounds__(256) void flash_attn_mma(float* __restrict__ AO)
{
    extern __shared__ float sm[];
    float* sQ = sm;                        // 128 x 132
    float* sK = sQ + FBR * ADP;            // 64 x 132
    float* sV = sK + 64 * ADP;             // 64 x 132
    float* sP = sV + 64 * ADP;             // 8 warps x 16 x 68

    const int b  = blockIdx.z, h = blockIdx.y;
    const int q0 = blockIdx.x * FBR;
    const int kh = h / NREP;
    const float* Qg = g_q + (((size_t)b * H_ + h) * S_ + q0) * D_;
    const float* Kg = g_k + ((size_t)b * KVH_ + kh) * (size_t)S_ * D_;
    const float* Vg = g_v + ((size_t)b * KVH_ + kh) * (size_t)S_ * D_;

    const int tid  = threadIdx.x;
    const int w    = tid >> 5;            // 0..7
    const int lane = tid & 31;
    const int lane4 = lane >> 2;
    const int lanek = lane & 3;

    // Q already tf32 bits, pre-scaled: straight copy (128 x 128)
    for (int e = tid; e < FBR * 32; e += 256) {
        int r = e >> 5, c = e & 31;
        *(float4*)&sQ[r * ADP + c * 4] = ((const float4*)Qg)[r * 32 + c];
    }

    float oacc[16][4];
#pragma unroll
    for (int nt = 0; nt < 16; nt++)
#pragma unroll
        for (int t = 0; t < 4; t++) oacc[nt][t] = 0.f;
    float m0 = -1e30f, m1 = -1e30f, l0 = 0.f, l1 = 0.f;

    const uint32_t* sQu = (const uint32_t*)sQ;
    const uint32_t* sKu = (const uint32_t*)sK;
    const uint32_t* sVu = (const uint32_t*)sV;
    uint32_t* sPw = (uint32_t*)sP + w * (16 * APP);

    for (int t0 = 0; t0 < S_; t0 += 64) {
        __syncthreads();
        for (int e = tid; e < 64 * 32; e += 256) {
            int r = e >> 5, c = e & 31;
            *(float4*)&sK[r * ADP + c * 4] = ((const float4*)(Kg + (size_t)t0 * D_))[r * 32 + c];
            *(float4*)&sV[r * ADP + c * 4] = ((const float4*)(Vg + (size_t)t0 * D_))[r * 32 + c];
        }
        __syncthreads();

        float sc[8][4];
#pragma unroll
        for (int nt = 0; nt < 8; nt++)
#pragma unroll
            for (int t = 0; t < 4; t++) sc[nt][t] = 0.f;

#pragma unroll
        for (int kk = 0; kk < 16; kk++) {
            uint32_t a[4];
            const uint32_t* qp = sQu + (w * 16 + lane4) * ADP + kk * 8 + lanek;
            a[0] = qp[0]; a[1] = qp[8 * ADP]; a[2] = qp[4]; a[3] = qp[8 * ADP + 4];
#pragma unroll
            for (int nt = 0; nt < 8; nt++) {
                uint32_t bb[2];
                const uint32_t* kp = sKu + (nt * 8 + lane4) * ADP + kk * 8 + lanek;
                bb[0] = kp[0]; bb[1] = kp[4];
                mma_tf32(sc[nt], a, bb);
            }
        }

        float mx0 = -1e30f, mx1 = -1e30f;
#pragma unroll
        for (int nt = 0; nt < 8; nt++) {
            mx0 = fmaxf(mx0, fmaxf(sc[nt][0], sc[nt][1]));
            mx1 = fmaxf(mx1, fmaxf(sc[nt][2], sc[nt][3]));
        }
        mx0 = fmaxf(mx0, __shfl_xor_sync(0xffffffffu, mx0, 1));
        mx0 = fmaxf(mx0, __shfl_xor_sync(0xffffffffu, mx0, 2));
        mx1 = fmaxf(mx1, __shfl_xor_sync(0xffffffffu, mx1, 1));
        mx1 = fmaxf(mx1, __shfl_xor_sync(0xffffffffu, mx1, 2));
        float mn0 = fmaxf(m0, mx0), mn1 = fmaxf(m1, mx1);
        float cr0 = ex2f(m0 - mn0), cr1 = ex2f(m1 - mn1);

        float s0 = 0.f, s1 = 0.f;
#pragma unroll
        for (int nt = 0; nt < 8; nt++) {
            float p00 = ex2f(sc[nt][0] - mn0);
            float p01 = ex2f(sc[nt][1] - mn0);
            float p10 = ex2f(sc[nt][2] - mn1);
            float p11 = ex2f(sc[nt][3] - mn1);
            s0 += p00 + p01;
            s1 += p10 + p11;
            uint2 lo = make_uint2(f2tf32(p00), f2tf32(p01));
            uint2 hi = make_uint2(f2tf32(p10), f2tf32(p11));
            *(uint2*)&sPw[lane4 * APP + nt * 8 + 2 * lanek]       = lo;
            *(uint2*)&sPw[(lane4 + 8) * APP + nt * 8 + 2 * lanek] = hi;
        }
        s0 += __shfl_xor_sync(0xffffffffu, s0, 1);
        s0 += __shfl_xor_sync(0xffffffffu, s0, 2);
        s1 += __shfl_xor_sync(0xffffffffu, s1, 1);
        s1 += __shfl_xor_sync(0xffffffffu, s1, 2);
        l0 = l0 * cr0 + s0;
        l1 = l1 * cr1 + s1;
        m0 = mn0; m1 = mn1;

#pragma unroll
        for (int nt = 0; nt < 16; nt++) {
            oacc[nt][0] *= cr0; oacc[nt][1] *= cr0;
            oacc[nt][2] *= cr1; oacc[nt][3] *= cr1;
        }
        __syncwarp();

#pragma unroll
        for (int kk = 0; kk < 8; kk++) {
            uint32_t a[4];
            const uint32_t* pp = sPw + lane4 * APP + kk * 8 + lanek;
            a[0] = pp[0]; a[1] = pp[8 * APP]; a[2] = pp[4]; a[3] = pp[8 * APP + 4];
#pragma unroll
            for (int nt = 0; nt < 16; nt++) {
                uint32_t bb[2];
                const uint32_t* vp = sVu + (kk * 8 + lanek) * ADP + nt * 8 + lane4;
                bb[0] = vp[0]; bb[1] = vp[4 * ADP];
                mma_tf32(oacc[nt], a, bb);
            }
        }
        __syncwarp();
    }

    float i0 = 1.f / l0, i1 = 1.f / l1;
    int row0 = q0 + w * 16 + lane4;
    uint32_t* O0 = (uint32_t*)AO + ((size_t)(b * S_ + row0) * H_ + h) * D_;
    uint32_t* O1 = O0 + (size_t)8 * H_ * D_;
#pragma unroll
    for (int nt = 0; nt < 16; nt++) {
        int col = nt * 8 + 2 * lanek;
        *(uint2*)&O0[col] = make_uint2(f2tf32(oacc[nt][0] * i0), f2tf32(oacc[nt][1] * i0));
        *(uint2*)&O1[col] = make_uint2(f2tf32(oacc[nt][2] * i1), f2tf32(oacc[nt][3] * i1));
    }
}

// ---------------------------------------------------------------------------
extern "C" void kernel_launch(void* const* d_in, const int* in_sizes, int n_in,
                              void* d_out, int out_size)
{
    const float* hidden = (const float*)d_in[0];
    const float* cosb   = (const float*)d_in[1];
    const float* sinb   = (const float*)d_in[2];
    const float* qkv_w  = (const float*)d_in[3];
    const float* o_w    = (const float*)d_in[4];
    const float* qnw    = (const float*)d_in[5];
    const float* knw    = (const float*)d_in[6];
    float* out = (float*)d_out;

    float *qkvp, *aop, *htp, *w1p, *w2p;
    cudaGetSymbolAddress((void**)&qkvp, g_qkv);
    cudaGetSymbolAddress((void**)&aop,  g_ao);
    cudaGetSymbolAddress((void**)&htp,  g_ht);
    cudaGetSymbolAddress((void**)&w1p,  g_w1);
    cudaGetSymbolAddress((void**)&w2p,  g_w2);

    cudaFuncSetAttribute(gemm_mma, cudaFuncAttributeMaxDynamicSharedMemorySize,
                         G_DYN_SMEM);
    cudaFuncSetAttribute(flash_attn_mma, cudaFuncAttributeMaxDynamicSharedMemorySize,
                         ATTN_SMEM);

    // 0) One-time tf32 pre-convert of GEMM inputs
    int nh = MTOK * HID_ / 4, nw1 = QKVN * HID_ / 4, nw2 = HID_ * HID_ / 4;
    cvt_tf32<<<(nh  + 255) / 256, 256>>>(hidden, htp, nh);
    cvt_tf32<<<(nw1 + 255) / 256, 256>>>(qkv_w,  w1p, nw1);
    cvt_tf32<<<(nw2 + 255) / 256, 256>>>(o_w,    w2p, nw2);

    // 1) QKV projection (tf32 mma.sync, 128x64 CTA, 3 CTAs/SM)
    dim3 g1(QKVN / GBN, MTOK / GBM);
    gemm_mma<<<g1, 256, G_DYN_SMEM>>>(htp, w1p, qkvp, MTOK, QKVN, HID_);

    // 2) RoPE + RMSNorm + scatter (emits tf32 bits)
    dim3 g2(H_ + 2 * KVH_, MTOK);
    rope_norm<<<g2, 128>>>(cosb, sinb, qnw, knw);

    // 3) Attention (tf32 mma.sync flash, BR=128, 8 warps)
    dim3 g3(S_ / FBR, H_, B_);
    flash_attn_mma<<<g3, 256, ATTN_SMEM>>>(aop);

    // 4) O projection (tf32 mma.sync)
    dim3 g4(HID_ / GBN, MTOK / GBM);
    gemm_mma<<<g4, 256, G_DYN_SMEM>>>(aop, w2p, out, MTOK, HID_, H_ * D_);
}

// round 9
// speedup vs baseline: 1.2967x; 1.0217x over previous
#include <cuda_runtime.h>
#include <cstdint>
#include <math.h>

// Problem constants
#define B_    2
#define S_    2048
#define HID_  4096
#define H_    32
#define KVH_  8
#define D_    128
#define NREP  (H_/KVH_)                 // 4
#define QKVN  (HID_ + 2*KVH_*D_)        // 6144
#define MTOK  (B_*S_)                   // 4096

// Scratch (static device globals; no runtime allocation allowed)
__device__ float g_qkv[(size_t)MTOK * QKVN];            // [tok][6144] fp32
__device__ float g_q  [(size_t)B_*H_*S_*D_];            // tf32 bits, pre-scaled
__device__ float g_k  [(size_t)B_*KVH_*S_*D_];          // tf32 bits
__device__ float g_v  [(size_t)B_*KVH_*S_*D_];          // tf32 bits
__device__ float g_ao [(size_t)MTOK * H_*D_];           // tf32 bits
__device__ float g_ht [(size_t)MTOK * HID_];            // hidden, tf32 bits
__device__ float g_w1 [(size_t)QKVN * HID_];            // qkv_w, tf32 bits
__device__ float g_w2 [(size_t)HID_ * HID_];            // o_w, tf32 bits

__device__ __forceinline__ uint32_t f2tf32(float f) {
    uint32_t r;
    asm("cvt.rna.tf32.f32 %0, %1;" : "=r"(r) : "f"(f));
    return r;
}
__device__ __forceinline__ float ex2f(float x) {
    float y;
    asm("ex2.approx.f32 %0, %1;" : "=f"(y) : "f"(x));
    return y;
}
__device__ __forceinline__ void mma_tf32(float* c, const uint32_t* a, const uint32_t* b) {
    asm volatile(
        "mma.sync.aligned.m16n8k8.row.col.f32.tf32.tf32.f32 "
        "{%0,%1,%2,%3}, {%4,%5,%6,%7}, {%8,%9}, {%0,%1,%2,%3};"
        : "+f"(c[0]), "+f"(c[1]), "+f"(c[2]), "+f"(c[3])
        : "r"(a[0]), "r"(a[1]), "r"(a[2]), "r"(a[3]), "r"(b[0]), "r"(b[1]));
}
__device__ __forceinline__ void cp_async16(uint32_t saddr, const void* gaddr) {
    asm volatile("cp.async.cg.shared.global [%0], [%1], 16;"
                 :: "r"(saddr), "l"(gaddr) : "memory");
}

// ---------------------------------------------------------------------------
// One-time tf32 pre-convert (elementwise, vectorized)
// ---------------------------------------------------------------------------
__global__ __launch_bounds__(256) void cvt_tf32(
    const float* __restrict__ in, float* __restrict__ out, int n4)
{
    int i = blockIdx.x * 256 + threadIdx.x;
    if (i >= n4) return;
    float4 v = ((const float4*)in)[i];
    uint4 u;
    u.x = f2tf32(v.x); u.y = f2tf32(v.y); u.z = f2tf32(v.z); u.w = f2tf32(v.w);
    ((uint4*)out)[i] = u;
}

// ===========================================================================
// tf32 mma.sync GEMM (NT): C = A * B^T, inputs pre-rounded tf32 bits.
// CTA tile 128x64, 8 warps (4x2), warp tile 32x32. BK=16, 3-stage cp.async.
// launch_bounds(256,4): regs capped at 64 -> 4 CTAs/SM = 32 warps.
// ===========================================================================
#define GBM 128
#define GBN 64
#define GBK 16
#define GSTRIDE 20
#define GA_FLOATS (GBM * GSTRIDE)               // 2560
#define GB_FLOATS (GBN * GSTRIDE)               // 1280
#define G_STAGE_FLOATS (GA_FLOATS + GB_FLOATS)  // 3840 floats = 15360 B
#define G_NSTAGE 3
#define G_DYN_SMEM (G_NSTAGE * G_STAGE_FLOATS * 4)   // 46080 bytes

__global__ __launch_bounds__(256, 4) void gemm_mma(
    const float* __restrict__ A, const float* __restrict__ Bm,
    float* __restrict__ C, int M, int N, int K)
{
    extern __shared__ float sdyn[];
    const uint32_t sbase = (uint32_t)__cvta_generic_to_shared(sdyn);

    const int tid  = threadIdx.x;
    const int wid  = tid >> 5;
    const int lane = tid & 31;
    const int warp_m = wid >> 1;          // 0..3
    const int warp_n = wid & 1;           // 0..1
    const int lane4 = lane >> 2;          // 0..7
    const int lanek = lane & 3;           // 0..3
    const int m0 = blockIdx.y * GBM;
    const int n0 = blockIdx.x * GBN;
    const int NK = K >> 4;

    const int ra  = tid >> 1;
    const int ca  = (tid & 1) * 2;
    const int rb  = tid >> 2;
    const int cb  = tid & 3;
    const float* Ag = A  + (size_t)(m0 + ra) * K;
    const float* Bg = Bm + (size_t)(n0 + rb) * K;
    const uint32_t sArow = sbase + (uint32_t)ra * (GSTRIDE * 4);
    const uint32_t sBrow = sbase + GA_FLOATS * 4 + (uint32_t)rb * (GSTRIDE * 4);

    // Prologue: fill stages 0,1
#pragma unroll
    for (int s = 0; s < G_NSTAGE - 1; s++) {
        uint32_t so = (uint32_t)s * (G_STAGE_FLOATS * 4);
        cp_async16(sArow + so + (ca    ) * 16, Ag + s * GBK + (ca    ) * 4);
        cp_async16(sArow + so + (ca + 1) * 16, Ag + s * GBK + (ca + 1) * 4);
        cp_async16(sBrow + so + cb * 16,       Bg + s * GBK + cb * 4);
        asm volatile("cp.async.commit_group;" ::: "memory");
    }

    float acc[2][4][4];
#pragma unroll
    for (int i = 0; i < 2; i++)
#pragma unroll
        for (int j = 0; j < 4; j++)
#pragma unroll
            for (int t = 0; t < 4; t++) acc[i][j][t] = 0.f;

    const int arow_off = (warp_m * 32 + lane4) * GSTRIDE + lanek;
    const int brow_off = (warp_n * 32 + lane4) * GSTRIDE + lanek;

    for (int it = 0; it < NK; it++) {
        asm volatile("cp.async.wait_group %0;" :: "n"(G_NSTAGE - 2) : "memory");
        __syncthreads();

        int itn = it + G_NSTAGE - 1;
        if (itn < NK) {
            uint32_t so = (uint32_t)(itn % G_NSTAGE) * (G_STAGE_FLOATS * 4);
            cp_async16(sArow + so + (ca    ) * 16, Ag + itn * GBK + (ca    ) * 4);
            cp_async16(sArow + so + (ca + 1) * 16, Ag + itn * GBK + (ca + 1) * 4);
            cp_async16(sBrow + so + cb * 16,       Bg + itn * GBK + cb * 4);
        }
        asm volatile("cp.async.commit_group;" ::: "memory");

        const uint32_t* sA = (const uint32_t*)(sdyn + (it % G_NSTAGE) * G_STAGE_FLOATS);
        const uint32_t* sB = sA + GA_FLOATS;

#pragma unroll
        for (int ks = 0; ks < 2; ks++) {
            const int kb = ks * 8;
            uint32_t af[2][4], bf[4][2];
#pragma unroll
            for (int mt = 0; mt < 2; mt++) {
                const uint32_t* ap = sA + arow_off + mt * (16 * GSTRIDE) + kb;
                af[mt][0] = ap[0];
                af[mt][1] = ap[8 * GSTRIDE];
                af[mt][2] = ap[4];
                af[mt][3] = ap[8 * GSTRIDE + 4];
            }
#pragma unroll
            for (int nt = 0; nt < 4; nt++) {
                const uint32_t* bp = sB + brow_off + nt * (8 * GSTRIDE) + kb;
                bf[nt][0] = bp[0];
                bf[nt][1] = bp[4];
            }
#pragma unroll
            for (int mt = 0; mt < 2; mt++)
#pragma unroll
                for (int nt = 0; nt < 4; nt++)
                    mma_tf32(acc[mt][nt], af[mt], bf[nt]);
        }
    }

#pragma unroll
    for (int mt = 0; mt < 2; mt++) {
#pragma unroll
        for (int nt = 0; nt < 4; nt++) {
            int row = m0 + warp_m * 32 + mt * 16 + lane4;
            int col = n0 + warp_n * 32 + nt * 8 + lanek * 2;
            *(float2*)&C[(size_t)row * N + col] =
                make_float2(acc[mt][nt][0], acc[mt][nt][1]);
            *(float2*)&C[(size_t)(row + 8) * N + col] =
                make_float2(acc[mt][nt][2], acc[mt][nt][3]);
        }
    }
}

// ---------------------------------------------------------------------------
// RoPE + per-head RMSNorm + scatter, one block per TOKEN.
// 128 threads = 4 warps; warp w handles heads w, w+4, ... cos/sin/norm-weights
// loaded into registers once. Rotate-half pairs (d, d±64) live in-thread.
// Writes tf32 bits (Q pre-scaled by scale*log2e).
// ---------------------------------------------------------------------------
__global__ __launch_bounds__(128) void rope_norm(
    const float* __restrict__ cosb, const float* __restrict__ sinb,
    const float* __restrict__ qw,   const float* __restrict__ kw)
{
    const int tok = blockIdx.x;
    const int b = tok / S_, s = tok % S_;
    const int tid = threadIdx.x;
    const int w = tid >> 5, lane = tid & 31;
    const float QSC = 0.08838834764831845f * 1.4426950408889634f;

    const float* row = g_qkv + (size_t)tok * QKVN;
    float c4[4], s4[4], qw4[4], kw4[4];
#pragma unroll
    for (int j = 0; j < 4; j++) {
        int d = lane + 32 * j;
        c4[j]  = cosb[((size_t)b * S_ + s) * D_ + d];
        s4[j]  = sinb[((size_t)b * S_ + s) * D_ + d];
        qw4[j] = qw[d];
        kw4[j] = kw[d];
    }

    // Q heads (0..31) and K heads (32..39): RoPE + RMSNorm
    for (int hh = w; hh < H_ + KVH_; hh += 4) {
        int off = (hh < H_) ? hh * D_ : H_ * D_ + (hh - H_) * D_;
        float x[4], y[4];
#pragma unroll
        for (int j = 0; j < 4; j++) x[j] = row[off + lane + 32 * j];
        y[0] = x[0] * c4[0] - x[2] * s4[0];
        y[1] = x[1] * c4[1] - x[3] * s4[1];
        y[2] = x[2] * c4[2] + x[0] * s4[2];
        y[3] = x[3] * c4[3] + x[1] * s4[3];
        float v2 = y[0] * y[0] + y[1] * y[1] + y[2] * y[2] + y[3] * y[3];
#pragma unroll
        for (int o = 16; o; o >>= 1) v2 += __shfl_xor_sync(0xffffffffu, v2, o);
        float inv = rsqrtf(v2 * (1.f / D_) + 1e-6f);

        if (hh < H_) {
            uint32_t* dst = (uint32_t*)g_q + (((size_t)b * H_ + hh) * S_ + s) * D_;
#pragma unroll
            for (int j = 0; j < 4; j++)
                dst[lane + 32 * j] = f2tf32(qw4[j] * y[j] * inv * QSC);
        } else {
            uint32_t* dst = (uint32_t*)g_k +
                (((size_t)b * KVH_ + (hh - H_)) * S_ + s) * D_;
#pragma unroll
            for (int j = 0; j < 4; j++)
                dst[lane + 32 * j] = f2tf32(kw4[j] * y[j] * inv);
        }
    }

    // V heads: copy + tf32 round
    for (int kv = w; kv < KVH_; kv += 4) {
        const float* src = row + H_ * D_ + KVH_ * D_ + kv * D_;
        uint32_t* dst = (uint32_t*)g_v + (((size_t)b * KVH_ + kv) * S_ + s) * D_;
#pragma unroll
        for (int j = 0; j < 4; j++)
            dst[lane + 32 * j] = f2tf32(src[lane + 32 * j]);
    }
}

// ---------------------------------------------------------------------------
// Flash attention with tf32 mma.sync. BR=128 (8 warps, 256 threads), BC=64,
// D=128. Inputs pre-converted tf32 bits. Output tf32 bits -> g_ao.
// ---------------------------------------------------------------------------
#define FBR 128
#define ADP 132
#define APP 68
#define ATTN_SMEM ((FBR * ADP + 2 * 64 * ADP + 8 * 16 * APP) * 4)  // 169984 B

__global__ __launch_bounds__(256) void flash_attn_mma(float* __restrict__ AO)
{
    extern __shared__ float sm[];
    float* sQ = sm;                        // 128 x 132
    float* sK = sQ + FBR * ADP;            // 64 x 132
    float* sV = sK + 64 * ADP;             // 64 x 132
    float* sP = sV + 64 * ADP;             // 8 warps x 16 x 68

    const int b  = blockIdx.z, h = blockIdx.y;
    const int q0 = blockIdx.x * FBR;
    const int kh = h / NREP;
    const float* Qg = g_q + (((size_t)b * H_ + h) * S_ + q0) * D_;
    const float* Kg = g_k + ((size_t)b * KVH_ + kh) * (size_t)S_ * D_;
    const float* Vg = g_v + ((size_t)b * KVH_ + kh) * (size_t)S_ * D_;

    const int tid  = threadIdx.x;
    const int w    = tid >> 5;
    const int lane = tid & 31;
    const int lane4 = lane >> 2;
    const int lanek = lane & 3;

    for (int e = tid; e < FBR * 32; e += 256) {
        int r = e >> 5, c = e & 31;
        *(float4*)&sQ[r * ADP + c * 4] = ((const float4*)Qg)[r * 32 + c];
    }

    float oacc[16][4];
#pragma unroll
    for (int nt = 0; nt < 16; nt++)
#pragma unroll
        for (int t = 0; t < 4; t++) oacc[nt][t] = 0.f;
    float m0 = -1e30f, m1 = -1e30f, l0 = 0.f, l1 = 0.f;

    const uint32_t* sQu = (const uint32_t*)sQ;
    const uint32_t* sKu = (const uint32_t*)sK;
    const uint32_t* sVu = (const uint32_t*)sV;
    uint32_t* sPw = (uint32_t*)sP + w * (16 * APP);

    for (int t0 = 0; t0 < S_; t0 += 64) {
        __syncthreads();
        for (int e = tid; e < 64 * 32; e += 256) {
            int r = e >> 5, c = e & 31;
            *(float4*)&sK[r * ADP + c * 4] = ((const float4*)(Kg + (size_t)t0 * D_))[r * 32 + c];
            *(float4*)&sV[r * ADP + c * 4] = ((const float4*)(Vg + (size_t)t0 * D_))[r * 32 + c];
        }
        __syncthreads();

        float sc[8][4];
#pragma unroll
        for (int nt = 0; nt < 8; nt++)
#pragma unroll
            for (int t = 0; t < 4; t++) sc[nt][t] = 0.f;

#pragma unroll
        for (int kk = 0; kk < 16; kk++) {
            uint32_t a[4];
            const uint32_t* qp = sQu + (w * 16 + lane4) * ADP + kk * 8 + lanek;
            a[0] = qp[0]; a[1] = qp[8 * ADP]; a[2] = qp[4]; a[3] = qp[8 * ADP + 4];
#pragma unroll
            for (int nt = 0; nt < 8; nt++) {
                uint32_t bb[2];
                const uint32_t* kp = sKu + (nt * 8 + lane4) * ADP + kk * 8 + lanek;
                bb[0] = kp[0]; bb[1] = kp[4];
                mma_tf32(sc[nt], a, bb);
            }
        }

        float mx0 = -1e30f, mx1 = -1e30f;
#pragma unroll
        for (int nt = 0; nt < 8; nt++) {
            mx0 = fmaxf(mx0, fmaxf(sc[nt][0], sc[nt][1]));
            mx1 = fmaxf(mx1, fmaxf(sc[nt][2], sc[nt][3]));
        }
        mx0 = fmaxf(mx0, __shfl_xor_sync(0xffffffffu, mx0, 1));
        mx0 = fmaxf(mx0, __shfl_xor_sync(0xffffffffu, mx0, 2));
        mx1 = fmaxf(mx1, __shfl_xor_sync(0xffffffffu, mx1, 1));
        mx1 = fmaxf(mx1, __shfl_xor_sync(0xffffffffu, mx1, 2));
        float mn0 = fmaxf(m0, mx0), mn1 = fmaxf(m1, mx1);
        float cr0 = ex2f(m0 - mn0), cr1 = ex2f(m1 - mn1);

        float s0 = 0.f, s1 = 0.f;
#pragma unroll
        for (int nt = 0; nt < 8; nt++) {
            float p00 = ex2f(sc[nt][0] - mn0);
            float p01 = ex2f(sc[nt][1] - mn0);
            float p10 = ex2f(sc[nt][2] - mn1);
            float p11 = ex2f(sc[nt][3] - mn1);
            s0 += p00 + p01;
            s1 += p10 + p11;
            uint2 lo = make_uint2(f2tf32(p00), f2tf32(p01));
            uint2 hi = make_uint2(f2tf32(p10), f2tf32(p11));
            *(uint2*)&sPw[lane4 * APP + nt * 8 + 2 * lanek]       = lo;
            *(uint2*)&sPw[(lane4 + 8) * APP + nt * 8 + 2 * lanek] = hi;
        }
        s0 += __shfl_xor_sync(0xffffffffu, s0, 1);
        s0 += __shfl_xor_sync(0xffffffffu, s0, 2);
        s1 += __shfl_xor_sync(0xffffffffu, s1, 1);
        s1 += __shfl_xor_sync(0xffffffffu, s1, 2);
        l0 = l0 * cr0 + s0;
        l1 = l1 * cr1 + s1;
        m0 = mn0; m1 = mn1;

#pragma unroll
        for (int nt = 0; nt < 16; nt++) {
            oacc[nt][0] *= cr0; oacc[nt][1] *= cr0;
            oacc[nt][2] *= cr1; oacc[nt][3] *= cr1;
        }
        __syncwarp();

#pragma unroll
        for (int kk = 0; kk < 8; kk++) {
            uint32_t a[4];
            const uint32_t* pp = sPw + lane4 * APP + kk * 8 + lanek;
            a[0] = pp[0]; a[1] = pp[8 * APP]; a[2] = pp[4]; a[3] = pp[8 * APP + 4];
#pragma unroll
            for (int nt = 0; nt < 16; nt++) {
                uint32_t bb[2];
                const uint32_t* vp = sVu + (kk * 8 + lanek) * ADP + nt * 8 + lane4;
                bb[0] = vp[0]; bb[1] = vp[4 * ADP];
                mma_tf32(oacc[nt], a, bb);
            }
        }
        __syncwarp();
    }

    float i0 = 1.f / l0, i1 = 1.f / l1;
    int row0 = q0 + w * 16 + lane4;
    uint32_t* O0 = (uint32_t*)AO + ((size_t)(b * S_ + row0) * H_ + h) * D_;
    uint32_t* O1 = O0 + (size_t)8 * H_ * D_;
#pragma unroll
    for (int nt = 0; nt < 16; nt++) {
        int col = nt * 8 + 2 * lanek;
        *(uint2*)&O0[col] = make_uint2(f2tf32(oacc[nt][0] * i0), f2tf32(oacc[nt][1] * i0));
        *(uint2*)&O1[col] = make_uint2(f2tf32(oacc[nt][2] * i1), f2tf32(oacc[nt][3] * i1));
    }
}

// ---------------------------------------------------------------------------
extern "C" void kernel_launch(void* const* d_in, const int* in_sizes, int n_in,
                              void* d_out, int out_size)
{
    const float* hidden = (const float*)d_in[0];
    const float* cosb   = (const float*)d_in[1];
    const float* sinb   = (const float*)d_in[2];
    const float* qkv_w  = (const float*)d_in[3];
    const float* o_w    = (const float*)d_in[4];
    const float* qnw    = (const float*)d_in[5];
    const float* knw    = (const float*)d_in[6];
    float* out = (float*)d_out;

    float *qkvp, *aop, *htp, *w1p, *w2p;
    cudaGetSymbolAddress((void**)&qkvp, g_qkv);
    cudaGetSymbolAddress((void**)&aop,  g_ao);
    cudaGetSymbolAddress((void**)&htp,  g_ht);
    cudaGetSymbolAddress((void**)&w1p,  g_w1);
    cudaGetSymbolAddress((void**)&w2p,  g_w2);

    cudaFuncSetAttribute(gemm_mma, cudaFuncAttributeMaxDynamicSharedMemorySize,
                         G_DYN_SMEM);
    cudaFuncSetAttribute(flash_attn_mma, cudaFuncAttributeMaxDynamicSharedMemorySize,
                         ATTN_SMEM);

    // 0) One-time tf32 pre-convert of GEMM inputs
    int nh = MTOK * HID_ / 4, nw1 = QKVN * HID_ / 4, nw2 = HID_ * HID_ / 4;
    cvt_tf32<<<(nh  + 255) / 256, 256>>>(hidden, htp, nh);
    cvt_tf32<<<(nw1 + 255) / 256, 256>>>(qkv_w,  w1p, nw1);
    cvt_tf32<<<(nw2 + 255) / 256, 256>>>(o_w,    w2p, nw2);

    // 1) QKV projection (tf32 mma.sync, 4 CTAs/SM)
    dim3 g1(QKVN / GBN, MTOK / GBM);
    gemm_mma<<<g1, 256, G_DYN_SMEM>>>(htp, w1p, qkvp, MTOK, QKVN, HID_);

    // 2) RoPE + RMSNorm + scatter (one block per token)
    rope_norm<<<MTOK, 128>>>(cosb, sinb, qnw, knw);

    // 3) Attention (tf32 mma.sync flash, BR=128)
    dim3 g3(S_ / FBR, H_, B_);
    flash_attn_mma<<<g3, 256, ATTN_SMEM>>>(aop);

    // 4) O projection (tf32 mma.sync)
    dim3 g4(HID_ / GBN, MTOK / GBM);
    gemm_mma<<<g4, 256, G_DYN_SMEM>>>(aop, w2p, out, MTOK, HID_, H_ * D_);
}